// round 2
// baseline (speedup 1.0000x reference)
#include <cuda_runtime.h>
#include <math.h>

// Problem constants
#define BATCH   2
#define SEQ     4096
#define DMODEL  512
#define NHEADS  8
#define DK      64
#define MROWS   (BATCH*SEQ)          // 8192

// Scratch buffers (device globals: allocation-free rule)
__device__ float g_Q[MROWS*DMODEL];
__device__ float g_K[MROWS*DMODEL];
__device__ float g_V[MROWS*DMODEL];
__device__ float g_C[MROWS*DMODEL];

// ---------------------------------------------------------------------------
// GEMM: C[M,N] = A[M,K] @ W[N,K]^T + bias[N]      (torch Linear semantics)
// BM=128, BN=128, BK=16, 256 threads, 8x8 micro-tile
// ---------------------------------------------------------------------------
__global__ void __launch_bounds__(256, 2) gemm_nt_bias(
    const float* __restrict__ A, const float* __restrict__ W,
    const float* __restrict__ bias, float* __restrict__ C,
    int M, int N, int K)
{
    constexpr int BM = 128, BN = 128, BK = 16;
    constexpr int LDA = BM + 4;
    __shared__ float As[BK][LDA];
    __shared__ float Ws[BK][LDA];

    const int tid = threadIdx.x;
    const int tx = tid & 15, ty = tid >> 4;
    const int m0 = blockIdx.y * BM;
    const int n0 = blockIdx.x * BN;

    float acc[8][8];
#pragma unroll
    for (int i = 0; i < 8; i++)
#pragma unroll
        for (int j = 0; j < 8; j++) acc[i][j] = 0.f;

    for (int k0 = 0; k0 < K; k0 += BK) {
#pragma unroll
        for (int i = 0; i < 2; i++) {
            int slot = tid + i * 256;
            int r  = slot >> 2;
            int c4 = slot & 3;
            float4 a = *(const float4*)&A[(m0 + r) * K + k0 + c4 * 4];
            As[c4*4+0][r] = a.x; As[c4*4+1][r] = a.y;
            As[c4*4+2][r] = a.z; As[c4*4+3][r] = a.w;
            float4 w = *(const float4*)&W[(n0 + r) * K + k0 + c4 * 4];
            Ws[c4*4+0][r] = w.x; Ws[c4*4+1][r] = w.y;
            Ws[c4*4+2][r] = w.z; Ws[c4*4+3][r] = w.w;
        }
        __syncthreads();

#pragma unroll
        for (int k = 0; k < BK; k++) {
            float a[8], b[8];
            *(float4*)&a[0] = *(const float4*)&As[k][ty * 8];
            *(float4*)&a[4] = *(const float4*)&As[k][ty * 8 + 4];
            *(float4*)&b[0] = *(const float4*)&Ws[k][tx * 8];
            *(float4*)&b[4] = *(const float4*)&Ws[k][tx * 8 + 4];
#pragma unroll
            for (int i = 0; i < 8; i++)
#pragma unroll
                for (int j = 0; j < 8; j++)
                    acc[i][j] = fmaf(a[i], b[j], acc[i][j]);
        }
        __syncthreads();
    }

#pragma unroll
    for (int i = 0; i < 8; i++) {
        int m = m0 + ty * 8 + i;
#pragma unroll
        for (int j = 0; j < 8; j += 4) {
            int n = n0 + tx * 8 + j;
            float4 v;
            v.x = acc[i][j+0] + bias[n+0];
            v.y = acc[i][j+1] + bias[n+1];
            v.z = acc[i][j+2] + bias[n+2];
            v.w = acc[i][j+3] + bias[n+3];
            *(float4*)&C[m * N + n] = v;
        }
    }
}

// ---------------------------------------------------------------------------
// Flash attention (fp32)
// ---------------------------------------------------------------------------
#define QTILE 64
#define KTILE 64
#define LDT   68

__device__ __forceinline__ float ex2f(float x) {
    float y; asm("ex2.approx.ftz.f32 %0, %1;" : "=f"(y) : "f"(x)); return y;
}
__device__ __forceinline__ float redmax16(float v) {
#pragma unroll
    for (int m = 8; m > 0; m >>= 1)
        v = fmaxf(v, __shfl_xor_sync(0xffffffffu, v, m));
    return v;
}
__device__ __forceinline__ float redsum16(float v) {
#pragma unroll
    for (int m = 8; m > 0; m >>= 1)
        v += __shfl_xor_sync(0xffffffffu, v, m);
    return v;
}

__global__ void __launch_bounds__(256, 1) attn_kernel()
{
    extern __shared__ float sm[];
    float* Qt = sm;
    float* Kt = Qt + 64 * LDT;
    float* Pt = Kt + 64 * LDT;
    float* Vs = Pt + 64 * LDT;

    const int tid = threadIdx.x;
    const int tx = tid & 15, ty = tid >> 4;
    const int bh = blockIdx.y;
    const int b = bh >> 3, h = bh & 7;
    const int q0 = blockIdx.x * QTILE;
    const int base = (b * SEQ) * DMODEL + h * DK;

#pragma unroll
    for (int i = 0; i < 4; i++) {
        int slot = tid + i * 256;
        int r  = slot >> 4;
        int d4 = slot & 15;
        float4 q = *(const float4*)&g_Q[base + (q0 + r) * DMODEL + d4 * 4];
        Qt[(d4*4+0)*LDT + r] = q.x; Qt[(d4*4+1)*LDT + r] = q.y;
        Qt[(d4*4+2)*LDT + r] = q.z; Qt[(d4*4+3)*LDT + r] = q.w;
    }

    float m2[4], lsum[4], o[4][4];
#pragma unroll
    for (int i = 0; i < 4; i++) {
        m2[i] = -1e30f; lsum[i] = 0.f;
#pragma unroll
        for (int j = 0; j < 4; j++) o[i][j] = 0.f;
    }

    const float QKS = 0.18033688011112042f;   // log2(e)/sqrt(64)

    for (int kb = 0; kb < SEQ; kb += KTILE) {
#pragma unroll
        for (int i = 0; i < 4; i++) {
            int slot = tid + i * 256;
            int r  = slot >> 4;
            int d4 = slot & 15;
            float4 kv = *(const float4*)&g_K[base + (kb + r) * DMODEL + d4 * 4];
            Kt[(d4*4+0)*LDT + r] = kv.x; Kt[(d4*4+1)*LDT + r] = kv.y;
            Kt[(d4*4+2)*LDT + r] = kv.z; Kt[(d4*4+3)*LDT + r] = kv.w;
            float4 vv = *(const float4*)&g_V[base + (kb + r) * DMODEL + d4 * 4];
            *(float4*)&Vs[r * 64 + d4 * 4] = vv;
        }
        __syncthreads();

        float s[4][4];
#pragma unroll
        for (int i = 0; i < 4; i++)
#pragma unroll
            for (int j = 0; j < 4; j++) s[i][j] = 0.f;

#pragma unroll
        for (int k = 0; k < 64; k++) {
            float qa[4], ka[4];
            *(float4*)&qa[0] = *(const float4*)&Qt[k * LDT + ty * 4];
            *(float4*)&ka[0] = *(const float4*)&Kt[k * LDT + tx * 4];
#pragma unroll
            for (int i = 0; i < 4; i++)
#pragma unroll
                for (int j = 0; j < 4; j++)
                    s[i][j] = fmaf(qa[i], ka[j], s[i][j]);
        }

        float pr[4][4];
#pragma unroll
        for (int i = 0; i < 4; i++) {
            float rm = s[i][0];
#pragma unroll
            for (int j = 1; j < 4; j++) rm = fmaxf(rm, s[i][j]);
            rm = redmax16(rm * QKS);
            float mn = fmaxf(m2[i], rm);
            float alpha = ex2f(m2[i] - mn);
            m2[i] = mn;
            float rs = 0.f;
#pragma unroll
            for (int j = 0; j < 4; j++) {
                pr[i][j] = ex2f(fmaf(s[i][j], QKS, -mn));
                rs += pr[i][j];
            }
            rs = redsum16(rs);
            lsum[i] = lsum[i] * alpha + rs;
#pragma unroll
            for (int j = 0; j < 4; j++) o[i][j] *= alpha;
        }

#pragma unroll
        for (int j = 0; j < 4; j++) {
            float4 pv = make_float4(pr[0][j], pr[1][j], pr[2][j], pr[3][j]);
            *(float4*)&Pt[(tx * 4 + j) * LDT + ty * 4] = pv;
        }
        __syncthreads();

#pragma unroll
        for (int k = 0; k < 64; k++) {
            float pa[4], va[4];
            *(float4*)&pa[0] = *(const float4*)&Pt[k * LDT + ty * 4];
            *(float4*)&va[0] = *(const float4*)&Vs[k * 64 + tx * 4];
#pragma unroll
            for (int i = 0; i < 4; i++)
#pragma unroll
                for (int j = 0; j < 4; j++)
                    o[i][j] = fmaf(pa[i], va[j], o[i][j]);
        }
        __syncthreads();
    }

#pragma unroll
    for (int i = 0; i < 4; i++) {
        float inv = 1.f / lsum[i];
        float4 v = make_float4(o[i][0]*inv, o[i][1]*inv, o[i][2]*inv, o[i][3]*inv);
        *(float4*)&g_C[base + (q0 + ty * 4 + i) * DMODEL + tx * 4] = v;
    }
}

// ---------------------------------------------------------------------------
struct LaunchState {
    float *dQ, *dK, *dV, *dC;
    LaunchState() {
        cudaGetSymbolAddress((void**)&dQ, g_Q);
        cudaGetSymbolAddress((void**)&dK, g_K);
        cudaGetSymbolAddress((void**)&dV, g_V);
        cudaGetSymbolAddress((void**)&dC, g_C);
        const int smem_attn = (3 * 64 * LDT + 64 * 64) * (int)sizeof(float);
        cudaFuncSetAttribute(attn_kernel,
                             cudaFuncAttributeMaxDynamicSharedMemorySize, smem_attn);
    }
};

extern "C" void kernel_launch(void* const* d_in, const int* in_sizes, int n_in,
                              void* d_out, int out_size)
{
    static LaunchState st;

    const float* x  = (const float*)d_in[0];
    const float* Wq = (const float*)d_in[1];
    const float* bq = (const float*)d_in[2];
    const float* Wk = (const float*)d_in[3];
    const float* bk = (const float*)d_in[4];
    const float* Wv = (const float*)d_in[5];
    const float* bv = (const float*)d_in[6];
    const float* Wo = (const float*)d_in[7];
    const float* bo = (const float*)d_in[8];
    float* out = (float*)d_out;

    const int smem_attn = (3 * 64 * LDT + 64 * 64) * (int)sizeof(float); // 68608 B

    dim3 gg(DMODEL / 128, MROWS / 128);   // (4, 64)
    gemm_nt_bias<<<gg, 256>>>(x,  Wq, bq, st.dQ, MROWS, DMODEL, DMODEL);
    gemm_nt_bias<<<gg, 256>>>(x,  Wk, bk, st.dK, MROWS, DMODEL, DMODEL);
    gemm_nt_bias<<<gg, 256>>>(x,  Wv, bv, st.dV, MROWS, DMODEL, DMODEL);

    dim3 ga(SEQ / QTILE, BATCH * NHEADS); // (64, 16)
    attn_kernel<<<ga, 256, smem_attn>>>();

    gemm_nt_bias<<<gg, 256>>>(st.dC, Wo, bo, out, MROWS, DMODEL, DMODEL);
}

// round 6
// speedup vs baseline: 2.1846x; 2.1846x over previous
#include <cuda_runtime.h>
#include <cuda_bf16.h>
#include <cstdint>
#include <math.h>

// Problem constants
#define BATCH   2
#define SEQ     4096
#define DMODEL  512
#define NHEADS  8
#define DK      64
#define MROWS   (BATCH*SEQ)          // 8192

// Scratch buffers
__device__ float g_Q[MROWS*DMODEL];
__device__ float g_K[MROWS*DMODEL];
__device__ float g_V[MROWS*DMODEL];
__device__ float g_C[MROWS*DMODEL];

// ---------------------------------------------------------------------------
// fp32 SIMT GEMM: C[M,N] = A[M,K] @ W[N,K]^T + bias[N]
// ---------------------------------------------------------------------------
__global__ void __launch_bounds__(256, 2) gemm_nt_bias(
    const float* __restrict__ A, const float* __restrict__ W,
    const float* __restrict__ bias, float* __restrict__ C,
    int M, int N, int K)
{
    constexpr int BM = 128, BN = 128, BK = 16;
    constexpr int LDA = BM + 4;
    __shared__ float As[BK][LDA];
    __shared__ float Ws[BK][LDA];

    const int tid = threadIdx.x;
    const int tx = tid & 15, ty = tid >> 4;
    const int m0 = blockIdx.y * BM;
    const int n0 = blockIdx.x * BN;

    float acc[8][8];
#pragma unroll
    for (int i = 0; i < 8; i++)
#pragma unroll
        for (int j = 0; j < 8; j++) acc[i][j] = 0.f;

    for (int k0 = 0; k0 < K; k0 += BK) {
#pragma unroll
        for (int i = 0; i < 2; i++) {
            int slot = tid + i * 256;
            int r  = slot >> 2;
            int c4 = slot & 3;
            float4 a = *(const float4*)&A[(m0 + r) * K + k0 + c4 * 4];
            As[c4*4+0][r] = a.x; As[c4*4+1][r] = a.y;
            As[c4*4+2][r] = a.z; As[c4*4+3][r] = a.w;
            float4 w = *(const float4*)&W[(n0 + r) * K + k0 + c4 * 4];
            Ws[c4*4+0][r] = w.x; Ws[c4*4+1][r] = w.y;
            Ws[c4*4+2][r] = w.z; Ws[c4*4+3][r] = w.w;
        }
        __syncthreads();

#pragma unroll
        for (int k = 0; k < BK; k++) {
            float a[8], b[8];
            *(float4*)&a[0] = *(const float4*)&As[k][ty * 8];
            *(float4*)&a[4] = *(const float4*)&As[k][ty * 8 + 4];
            *(float4*)&b[0] = *(const float4*)&Ws[k][tx * 8];
            *(float4*)&b[4] = *(const float4*)&Ws[k][tx * 8 + 4];
#pragma unroll
            for (int i = 0; i < 8; i++)
#pragma unroll
                for (int j = 0; j < 8; j++)
                    acc[i][j] = fmaf(a[i], b[j], acc[i][j]);
        }
        __syncthreads();
    }

#pragma unroll
    for (int i = 0; i < 8; i++) {
        int m = m0 + ty * 8 + i;
#pragma unroll
        for (int j = 0; j < 8; j += 4) {
            int n = n0 + tx * 8 + j;
            float4 v;
            v.x = acc[i][j+0] + bias[n+0];
            v.y = acc[i][j+1] + bias[n+1];
            v.z = acc[i][j+2] + bias[n+2];
            v.w = acc[i][j+3] + bias[n+3];
            *(float4*)&C[m * N + n] = v;
        }
    }
}

// ---------------------------------------------------------------------------
// mma.sync helpers (sm_80+ path; works on plain sm_100 target)
// ---------------------------------------------------------------------------
__device__ __forceinline__ uint32_t smem_u32(const void* p) {
    uint32_t a;
    asm("{ .reg .u64 t; cvta.to.shared.u64 t, %1; cvt.u32.u64 %0, t; }" : "=r"(a) : "l"(p));
    return a;
}
__device__ __forceinline__ void ldmx4(uint32_t* r, uint32_t addr) {
    asm volatile("ldmatrix.sync.aligned.m8n8.x4.shared.b16 {%0,%1,%2,%3}, [%4];"
        : "=r"(r[0]), "=r"(r[1]), "=r"(r[2]), "=r"(r[3]) : "r"(addr));
}
__device__ __forceinline__ void mma16816(float* c, const uint32_t* a,
                                         uint32_t b0, uint32_t b1) {
    asm volatile("mma.sync.aligned.m16n8k16.row.col.f32.bf16.bf16.f32 "
        "{%0,%1,%2,%3}, {%4,%5,%6,%7}, {%8,%9}, {%0,%1,%2,%3};"
        : "+f"(c[0]), "+f"(c[1]), "+f"(c[2]), "+f"(c[3])
        : "r"(a[0]), "r"(a[1]), "r"(a[2]), "r"(a[3]), "r"(b0), "r"(b1));
}
__device__ __forceinline__ float ex2f(float x) {
    float y; asm("ex2.approx.ftz.f32 %0, %1;" : "=f"(y) : "f"(x)); return y;
}
// pack: low 16 = bf16(x), high 16 = bf16(y)
__device__ __forceinline__ uint32_t pack_bf16x2(float x, float y) {
    uint32_t r; asm("cvt.rn.bf16x2.f32 %0, %1, %2;" : "=r"(r) : "f"(y), "f"(x)); return r;
}
// hi/lo split of a float pair into two bf16x2 regs
__device__ __forceinline__ void split2(float x, float y, uint32_t& h, uint32_t& l) {
    h = pack_bf16x2(x, y);
    float hx = __uint_as_float(h << 16);
    float hy = __uint_as_float(h & 0xffff0000u);
    l = pack_bf16x2(x - hx, y - hy);
}

// ---------------------------------------------------------------------------
// HMMA flash attention, bf16 hi/lo 3-term split, no-rescale exp2 softmax.
// Grid (SEQ/128, B*H), 256 threads (8 warps, warp = 16 q-rows).
// smem (dynamic, 144B padded rows):
//   QH/QL [128][72]bf16, KH/KL [64][72], VTH/VTL (=V^T) [64][72]
// ---------------------------------------------------------------------------
#define LDKB 144                   // bytes per padded row (72 bf16)
#define OFF_QH 0
#define OFF_QL 18432
#define OFF_KH 36864
#define OFF_KL 46080
#define OFF_VH 55296
#define OFF_VL 64512
#define SM_ATTN_BYTES 73728

__global__ void __launch_bounds__(256, 2) attn_hmma()
{
    extern __shared__ char sm[];
    const int tid  = threadIdx.x;
    const int lane = tid & 31;
    const int w    = tid >> 5;

    const int bh = blockIdx.y;
    const int b = bh >> 3, hh = bh & 7;
    const int q0 = blockIdx.x * 128;
    const int gbase = b * SEQ * DMODEL + hh * DK;

    const uint32_t s0  = smem_u32(sm);
    const uint32_t QHs = s0 + OFF_QH, QLs = s0 + OFF_QL;
    const uint32_t KHs = s0 + OFF_KH, KLs = s0 + OFF_KL;
    const uint32_t VHs = s0 + OFF_VH, VLs = s0 + OFF_VL;

    // ---- Load Q tile (128 x 64), split to bf16 hi/lo ----
    {
        const float* src = g_Q + gbase + q0 * DMODEL;
#pragma unroll
        for (int it = 0; it < 8; it++) {
            int i = tid + it * 256;             // 0..2047
            int r = i >> 4, c4 = i & 15;        // row, float4 index (d = 4*c4)
            float4 v = *(const float4*)&src[r * DMODEL + c4 * 4];
            uint32_t h0, l0, h1, l1;
            split2(v.x, v.y, h0, l0);
            split2(v.z, v.w, h1, l1);
            uint32_t off = (uint32_t)(r * LDKB + c4 * 8);
            *(uint32_t*)(sm + OFF_QH + off)     = h0;
            *(uint32_t*)(sm + OFF_QH + off + 4) = h1;
            *(uint32_t*)(sm + OFF_QL + off)     = l0;
            *(uint32_t*)(sm + OFF_QL + off + 4) = l1;
        }
    }

    // Per-lane ldmatrix address components
    const uint32_t a_row  = (uint32_t)((w * 16 + (lane & 15)) * LDKB + ((lane >> 4) * 16));
    const uint32_t b_base = (uint32_t)((8 * ((lane >> 4) & 1) + (lane & 7)) * LDKB
                                       + (((lane >> 3) & 1) * 16));

    const float QKS = 0.18033688011112042f;     // log2(e)/sqrt(64)
    float O[8][4];
#pragma unroll
    for (int i = 0; i < 8; i++)
#pragma unroll
        for (int j = 0; j < 4; j++) O[i][j] = 0.f;
    float lsum0 = 0.f, lsum1 = 0.f;

    for (int kb = 0; kb < SEQ; kb += 64) {
        // ---- Load K tile (64 keys x 64 d), split hi/lo ----
        {
            const float* src = g_K + gbase + kb * DMODEL;
#pragma unroll
            for (int it = 0; it < 4; it++) {
                int i = tid + it * 256;         // 0..1023
                int r = i >> 4, c4 = i & 15;
                float4 v = *(const float4*)&src[r * DMODEL + c4 * 4];
                uint32_t h0, l0, h1, l1;
                split2(v.x, v.y, h0, l0);
                split2(v.z, v.w, h1, l1);
                uint32_t off = (uint32_t)(r * LDKB + c4 * 8);
                *(uint32_t*)(sm + OFF_KH + off)     = h0;
                *(uint32_t*)(sm + OFF_KH + off + 4) = h1;
                *(uint32_t*)(sm + OFF_KL + off)     = l0;
                *(uint32_t*)(sm + OFF_KL + off + 4) = l1;
            }
        }
        // ---- Load V tile transposed: Vt[d][key], split hi/lo ----
        {
            const float* src = g_V + gbase + kb * DMODEL;
            int key0 = (tid & 15) * 4;
            int d0   = (tid >> 4) * 4;
            float vv[4][4];
#pragma unroll
            for (int i = 0; i < 4; i++) {
                float4 x = *(const float4*)&src[(key0 + i) * DMODEL + d0];
                vv[i][0] = x.x; vv[i][1] = x.y; vv[i][2] = x.z; vv[i][3] = x.w;
            }
#pragma unroll
            for (int j = 0; j < 4; j++) {
                uint32_t h0, l0, h1, l1;
                split2(vv[0][j], vv[1][j], h0, l0);
                split2(vv[2][j], vv[3][j], h1, l1);
                uint32_t off = (uint32_t)((d0 + j) * LDKB + key0 * 2);
                *(uint32_t*)(sm + OFF_VH + off)     = h0;
                *(uint32_t*)(sm + OFF_VH + off + 4) = h1;
                *(uint32_t*)(sm + OFF_VL + off)     = l0;
                *(uint32_t*)(sm + OFF_VL + off + 4) = l1;
            }
        }
        __syncthreads();

        // ---- Scores S[16q x 64keys] per warp: 3-term split ----
        float S[8][4];
#pragma unroll
        for (int i = 0; i < 8; i++)
#pragma unroll
            for (int j = 0; j < 4; j++) S[i][j] = 0.f;

#pragma unroll
        for (int ks = 0; ks < 4; ks++) {
            uint32_t Ah[4], Al[4];
            ldmx4(Ah, QHs + a_row + ks * 32);
            ldmx4(Al, QLs + a_row + ks * 32);
#pragma unroll
            for (int ntp = 0; ntp < 4; ntp++) {
                uint32_t Bh[4], Bl[4];
                uint32_t baddr = b_base + ntp * (16 * LDKB) + ks * 32;
                ldmx4(Bh, KHs + baddr);
                ldmx4(Bl, KLs + baddr);
                mma16816(S[2*ntp],   Ah, Bh[0], Bh[1]);
                mma16816(S[2*ntp],   Ah, Bl[0], Bl[1]);
                mma16816(S[2*ntp],   Al, Bh[0], Bh[1]);
                mma16816(S[2*ntp+1], Ah, Bh[2], Bh[3]);
                mma16816(S[2*ntp+1], Ah, Bl[2], Bl[3]);
                mma16816(S[2*ntp+1], Al, Bh[2], Bh[3]);
            }
        }

        // ---- exp2 softmax (no max shift) ----
#pragma unroll
        for (int nt = 0; nt < 8; nt++) {
            float p0 = ex2f(S[nt][0] * QKS);
            float p1 = ex2f(S[nt][1] * QKS);
            float p2 = ex2f(S[nt][2] * QKS);
            float p3 = ex2f(S[nt][3] * QKS);
            S[nt][0] = p0; S[nt][1] = p1; S[nt][2] = p2; S[nt][3] = p3;
            lsum0 += p0 + p1;
            lsum1 += p2 + p3;
        }

        // ---- O += P @ V (3-term split); P from score fragments ----
#pragma unroll
        for (int j = 0; j < 4; j++) {          // key16 chunks
            uint32_t Ph[4], Pl[4];
            split2(S[2*j][0],   S[2*j][1],   Ph[0], Pl[0]);
            split2(S[2*j][2],   S[2*j][3],   Ph[1], Pl[1]);
            split2(S[2*j+1][0], S[2*j+1][1], Ph[2], Pl[2]);
            split2(S[2*j+1][2], S[2*j+1][3], Ph[3], Pl[3]);
#pragma unroll
            for (int dtp = 0; dtp < 4; dtp++) {
                uint32_t Vh[4], Vl[4];
                uint32_t vaddr = b_base + dtp * (16 * LDKB) + j * 32;
                ldmx4(Vh, VHs + vaddr);
                ldmx4(Vl, VLs + vaddr);
                mma16816(O[2*dtp],   Ph, Vh[0], Vh[1]);
                mma16816(O[2*dtp],   Ph, Vl[0], Vl[1]);
                mma16816(O[2*dtp],   Pl, Vh[0], Vh[1]);
                mma16816(O[2*dtp+1], Ph, Vh[2], Vh[3]);
                mma16816(O[2*dtp+1], Ph, Vl[2], Vl[3]);
                mma16816(O[2*dtp+1], Pl, Vh[2], Vh[3]);
            }
        }
        __syncthreads();
    }

    // ---- Normalize + write ----
    lsum0 += __shfl_xor_sync(0xffffffffu, lsum0, 1);
    lsum0 += __shfl_xor_sync(0xffffffffu, lsum0, 2);
    lsum1 += __shfl_xor_sync(0xffffffffu, lsum1, 1);
    lsum1 += __shfl_xor_sync(0xffffffffu, lsum1, 2);
    float inv0 = 1.f / lsum0;
    float inv1 = 1.f / lsum1;

    int r0 = q0 + w * 16 + (lane >> 2);
    int r1 = r0 + 8;
#pragma unroll
    for (int dt = 0; dt < 8; dt++) {
        int c = dt * 8 + 2 * (lane & 3);
        float2 u0 = make_float2(O[dt][0] * inv0, O[dt][1] * inv0);
        float2 u1 = make_float2(O[dt][2] * inv1, O[dt][3] * inv1);
        *(float2*)&g_C[gbase + r0 * DMODEL + c] = u0;
        *(float2*)&g_C[gbase + r1 * DMODEL + c] = u1;
    }
}

// ---------------------------------------------------------------------------
extern "C" void kernel_launch(void* const* d_in, const int* in_sizes, int n_in,
                              void* d_out, int out_size)
{
    static bool inited = false;
    static float *dQ, *dK, *dV, *dC;
    if (!inited) {
        cudaGetSymbolAddress((void**)&dQ, g_Q);
        cudaGetSymbolAddress((void**)&dK, g_K);
        cudaGetSymbolAddress((void**)&dV, g_V);
        cudaGetSymbolAddress((void**)&dC, g_C);
        cudaFuncSetAttribute(attn_hmma,
                             cudaFuncAttributeMaxDynamicSharedMemorySize, SM_ATTN_BYTES);
        inited = true;
    }

    const float* x  = (const float*)d_in[0];
    const float* Wq = (const float*)d_in[1];
    const float* bq = (const float*)d_in[2];
    const float* Wk = (const float*)d_in[3];
    const float* bk = (const float*)d_in[4];
    const float* Wv = (const float*)d_in[5];
    const float* bv = (const float*)d_in[6];
    const float* Wo = (const float*)d_in[7];
    const float* bo = (const float*)d_in[8];
    float* out = (float*)d_out;

    dim3 gg(DMODEL / 128, MROWS / 128);   // (4, 64)
    gemm_nt_bias<<<gg, 256>>>(x,  Wq, bq, dQ, MROWS, DMODEL, DMODEL);
    gemm_nt_bias<<<gg, 256>>>(x,  Wk, bk, dK, MROWS, DMODEL, DMODEL);
    gemm_nt_bias<<<gg, 256>>>(x,  Wv, bv, dV, MROWS, DMODEL, DMODEL);

    dim3 ga(SEQ / 128, BATCH * NHEADS);   // (32, 16)
    attn_hmma<<<ga, 256, SM_ATTN_BYTES>>>();

    gemm_nt_bias<<<gg, 256>>>(dC, Wo, bo, out, MROWS, DMODEL, DMODEL);
}

// round 7
// speedup vs baseline: 2.7365x; 1.2526x over previous
#include <cuda_runtime.h>
#include <cuda_bf16.h>
#include <cstdint>
#include <math.h>

// Problem constants
#define BATCH   2
#define SEQ     4096
#define DMODEL  512
#define NHEADS  8
#define DK      64
#define MROWS   (BATCH*SEQ)          // 8192

// Scratch buffers
__device__ float g_Q[MROWS*DMODEL];
__device__ float g_K[MROWS*DMODEL];
__device__ float g_V[MROWS*DMODEL];
__device__ float g_C[MROWS*DMODEL];

// ---------------------------------------------------------------------------
// mma.sync helpers (sm_80+ path; works on plain sm_100 target)
// ---------------------------------------------------------------------------
__device__ __forceinline__ uint32_t smem_u32(const void* p) {
    uint32_t a;
    asm("{ .reg .u64 t; cvta.to.shared.u64 t, %1; cvt.u32.u64 %0, t; }" : "=r"(a) : "l"(p));
    return a;
}
__device__ __forceinline__ void ldmx4(uint32_t* r, uint32_t addr) {
    asm volatile("ldmatrix.sync.aligned.m8n8.x4.shared.b16 {%0,%1,%2,%3}, [%4];"
        : "=r"(r[0]), "=r"(r[1]), "=r"(r[2]), "=r"(r[3]) : "r"(addr));
}
__device__ __forceinline__ void mma16816(float* c, const uint32_t* a,
                                         uint32_t b0, uint32_t b1) {
    asm volatile("mma.sync.aligned.m16n8k16.row.col.f32.bf16.bf16.f32 "
        "{%0,%1,%2,%3}, {%4,%5,%6,%7}, {%8,%9}, {%0,%1,%2,%3};"
        : "+f"(c[0]), "+f"(c[1]), "+f"(c[2]), "+f"(c[3])
        : "r"(a[0]), "r"(a[1]), "r"(a[2]), "r"(a[3]), "r"(b0), "r"(b1));
}
__device__ __forceinline__ float ex2f(float x) {
    float y; asm("ex2.approx.ftz.f32 %0, %1;" : "=f"(y) : "f"(x)); return y;
}
// pack: low 16 = bf16(x), high 16 = bf16(y)
__device__ __forceinline__ uint32_t pack_bf16x2(float x, float y) {
    uint32_t r; asm("cvt.rn.bf16x2.f32 %0, %1, %2;" : "=r"(r) : "f"(y), "f"(x)); return r;
}
// hi/lo split of a float pair into two bf16x2 regs
__device__ __forceinline__ void split2(float x, float y, uint32_t& h, uint32_t& l) {
    h = pack_bf16x2(x, y);
    float hx = __uint_as_float(h << 16);
    float hy = __uint_as_float(h & 0xffff0000u);
    l = pack_bf16x2(x - hx, y - hy);
}

// ---------------------------------------------------------------------------
// HMMA GEMM: C[M=8192,N=512] = A @ W^T + bias, bf16 hi/lo 3-term split.
// Block 128x128, BK=32, 256 threads; warp tile 32m x 64n (wm=w&3, wn=w>>2).
// smem rows padded to 80B (conflict-free ldmatrix: 80*r mod 128 tiles phases).
// ---------------------------------------------------------------------------
#define GLDK 80
#define GOFF_AH 0
#define GOFF_AL 10240
#define GOFF_WH 20480
#define GOFF_WL 30720

__global__ void __launch_bounds__(256, 2) gemm_hmma(
    const float* __restrict__ A, const float* __restrict__ W,
    const float* __restrict__ bias, float* __restrict__ C)
{
    __shared__ char sm[40960];
    const int tid  = threadIdx.x;
    const int lane = tid & 31;
    const int w    = tid >> 5;
    const int wm   = w & 3;          // m-quarter: 32 rows
    const int wn   = w >> 2;         // n-half: 64 cols
    const int m0   = blockIdx.y * 128;
    const int n0   = blockIdx.x * 128;

    const uint32_t s0 = smem_u32(sm);

    float acc[2][8][4];
#pragma unroll
    for (int mt = 0; mt < 2; mt++)
#pragma unroll
        for (int nt = 0; nt < 8; nt++)
#pragma unroll
            for (int q = 0; q < 4; q++) acc[mt][nt][q] = 0.f;

    // ldmatrix lane-address components
    const uint32_t a_base0 = (uint32_t)((wm * 32 + (lane & 15)) * GLDK + (lane >> 4) * 16);
    const uint32_t b_base0 = (uint32_t)((wn * 64 + 8 * ((lane >> 4) & 1) + (lane & 7)) * GLDK
                                        + (((lane >> 3) & 1) * 16));

    for (int k0 = 0; k0 < DMODEL; k0 += 32) {
        // ---- Load A,W 128x32 fp32 -> split hi/lo bf16 in smem ----
        {
            int r  = tid >> 1;
            int hf = tid & 1;
            const float* pa = A + (m0 + r) * DMODEL + k0 + hf * 16;
            const float* pw = W + (n0 + r) * DMODEL + k0 + hf * 16;
            uint32_t off = (uint32_t)(r * GLDK + hf * 32);
#pragma unroll
            for (int q = 0; q < 4; q++) {
                float4 va = *(const float4*)&pa[q * 4];
                uint32_t h0, l0, h1, l1;
                split2(va.x, va.y, h0, l0);
                split2(va.z, va.w, h1, l1);
                *(uint32_t*)(sm + GOFF_AH + off + q * 8)     = h0;
                *(uint32_t*)(sm + GOFF_AH + off + q * 8 + 4) = h1;
                *(uint32_t*)(sm + GOFF_AL + off + q * 8)     = l0;
                *(uint32_t*)(sm + GOFF_AL + off + q * 8 + 4) = l1;
                float4 vw = *(const float4*)&pw[q * 4];
                split2(vw.x, vw.y, h0, l0);
                split2(vw.z, vw.w, h1, l1);
                *(uint32_t*)(sm + GOFF_WH + off + q * 8)     = h0;
                *(uint32_t*)(sm + GOFF_WH + off + q * 8 + 4) = h1;
                *(uint32_t*)(sm + GOFF_WL + off + q * 8)     = l0;
                *(uint32_t*)(sm + GOFF_WL + off + q * 8 + 4) = l1;
            }
        }
        __syncthreads();

#pragma unroll
        for (int ks = 0; ks < 2; ks++) {
            uint32_t Ah[2][4], Al[2][4];
#pragma unroll
            for (int mt = 0; mt < 2; mt++) {
                uint32_t aaddr = a_base0 + (uint32_t)(mt * 16 * GLDK + ks * 32);
                ldmx4(Ah[mt], s0 + GOFF_AH + aaddr);
                ldmx4(Al[mt], s0 + GOFF_AL + aaddr);
            }
#pragma unroll
            for (int nt = 0; nt < 4; nt++) {
                uint32_t Bh[4], Bl[4];
                uint32_t baddr = b_base0 + (uint32_t)(nt * 16 * GLDK + ks * 32);
                ldmx4(Bh, s0 + GOFF_WH + baddr);
                ldmx4(Bl, s0 + GOFF_WL + baddr);
#pragma unroll
                for (int mt = 0; mt < 2; mt++) {
                    mma16816(acc[mt][2*nt],   Ah[mt], Bh[0], Bh[1]);
                    mma16816(acc[mt][2*nt],   Ah[mt], Bl[0], Bl[1]);
                    mma16816(acc[mt][2*nt],   Al[mt], Bh[0], Bh[1]);
                    mma16816(acc[mt][2*nt+1], Ah[mt], Bh[2], Bh[3]);
                    mma16816(acc[mt][2*nt+1], Ah[mt], Bl[2], Bl[3]);
                    mma16816(acc[mt][2*nt+1], Al[mt], Bh[2], Bh[3]);
                }
            }
        }
        __syncthreads();
    }

    // ---- Epilogue: + bias, fp32 store ----
#pragma unroll
    for (int mt = 0; mt < 2; mt++) {
        int r0 = m0 + wm * 32 + mt * 16 + (lane >> 2);
        int r1 = r0 + 8;
#pragma unroll
        for (int nt = 0; nt < 8; nt++) {
            int c = n0 + wn * 64 + nt * 8 + 2 * (lane & 3);
            float2 bb = *(const float2*)&bias[c];
            float2 u0 = make_float2(acc[mt][nt][0] + bb.x, acc[mt][nt][1] + bb.y);
            float2 u1 = make_float2(acc[mt][nt][2] + bb.x, acc[mt][nt][3] + bb.y);
            *(float2*)&C[r0 * DMODEL + c] = u0;
            *(float2*)&C[r1 * DMODEL + c] = u1;
        }
    }
}

// ---------------------------------------------------------------------------
// HMMA flash attention, bf16 hi/lo 3-term split, no-rescale exp2 softmax.
// Grid (SEQ/128, B*H), 256 threads (8 warps, warp = 16 q-rows).
// ---------------------------------------------------------------------------
#define LDKB 144
#define OFF_QH 0
#define OFF_QL 18432
#define OFF_KH 36864
#define OFF_KL 46080
#define OFF_VH 55296
#define OFF_VL 64512
#define SM_ATTN_BYTES 73728

__global__ void __launch_bounds__(256, 2) attn_hmma()
{
    extern __shared__ char sm[];
    const int tid  = threadIdx.x;
    const int lane = tid & 31;
    const int w    = tid >> 5;

    const int bh = blockIdx.y;
    const int b = bh >> 3, hh = bh & 7;
    const int q0 = blockIdx.x * 128;
    const int gbase = b * SEQ * DMODEL + hh * DK;

    const uint32_t s0  = smem_u32(sm);
    const uint32_t QHs = s0 + OFF_QH, QLs = s0 + OFF_QL;
    const uint32_t KHs = s0 + OFF_KH, KLs = s0 + OFF_KL;
    const uint32_t VHs = s0 + OFF_VH, VLs = s0 + OFF_VL;

    // ---- Load Q tile (128 x 64), split to bf16 hi/lo ----
    {
        const float* src = g_Q + gbase + q0 * DMODEL;
#pragma unroll
        for (int it = 0; it < 8; it++) {
            int i = tid + it * 256;
            int r = i >> 4, c4 = i & 15;
            float4 v = *(const float4*)&src[r * DMODEL + c4 * 4];
            uint32_t h0, l0, h1, l1;
            split2(v.x, v.y, h0, l0);
            split2(v.z, v.w, h1, l1);
            uint32_t off = (uint32_t)(r * LDKB + c4 * 8);
            *(uint32_t*)(sm + OFF_QH + off)     = h0;
            *(uint32_t*)(sm + OFF_QH + off + 4) = h1;
            *(uint32_t*)(sm + OFF_QL + off)     = l0;
            *(uint32_t*)(sm + OFF_QL + off + 4) = l1;
        }
    }

    const uint32_t a_row  = (uint32_t)((w * 16 + (lane & 15)) * LDKB + ((lane >> 4) * 16));
    const uint32_t b_base = (uint32_t)((8 * ((lane >> 4) & 1) + (lane & 7)) * LDKB
                                       + (((lane >> 3) & 1) * 16));

    const float QKS = 0.18033688011112042f;     // log2(e)/sqrt(64)
    float O[8][4];
#pragma unroll
    for (int i = 0; i < 8; i++)
#pragma unroll
        for (int j = 0; j < 4; j++) O[i][j] = 0.f;
    float lsum0 = 0.f, lsum1 = 0.f;

    for (int kb = 0; kb < SEQ; kb += 64) {
        // ---- Load K tile (64 keys x 64 d), split hi/lo ----
        {
            const float* src = g_K + gbase + kb * DMODEL;
#pragma unroll
            for (int it = 0; it < 4; it++) {
                int i = tid + it * 256;
                int r = i >> 4, c4 = i & 15;
                float4 v = *(const float4*)&src[r * DMODEL + c4 * 4];
                uint32_t h0, l0, h1, l1;
                split2(v.x, v.y, h0, l0);
                split2(v.z, v.w, h1, l1);
                uint32_t off = (uint32_t)(r * LDKB + c4 * 8);
                *(uint32_t*)(sm + OFF_KH + off)     = h0;
                *(uint32_t*)(sm + OFF_KH + off + 4) = h1;
                *(uint32_t*)(sm + OFF_KL + off)     = l0;
                *(uint32_t*)(sm + OFF_KL + off + 4) = l1;
            }
        }
        // ---- Load V tile transposed: Vt[d][key], split hi/lo ----
        {
            const float* src = g_V + gbase + kb * DMODEL;
            int key0 = (tid & 15) * 4;
            int d0   = (tid >> 4) * 4;
            float vv[4][4];
#pragma unroll
            for (int i = 0; i < 4; i++) {
                float4 x = *(const float4*)&src[(key0 + i) * DMODEL + d0];
                vv[i][0] = x.x; vv[i][1] = x.y; vv[i][2] = x.z; vv[i][3] = x.w;
            }
#pragma unroll
            for (int j = 0; j < 4; j++) {
                uint32_t h0, l0, h1, l1;
                split2(vv[0][j], vv[1][j], h0, l0);
                split2(vv[2][j], vv[3][j], h1, l1);
                uint32_t off = (uint32_t)((d0 + j) * LDKB + key0 * 2);
                *(uint32_t*)(sm + OFF_VH + off)     = h0;
                *(uint32_t*)(sm + OFF_VH + off + 4) = h1;
                *(uint32_t*)(sm + OFF_VL + off)     = l0;
                *(uint32_t*)(sm + OFF_VL + off + 4) = l1;
            }
        }
        __syncthreads();

        // ---- Scores S[16q x 64keys] per warp: 3-term split ----
        float S[8][4];
#pragma unroll
        for (int i = 0; i < 8; i++)
#pragma unroll
            for (int j = 0; j < 4; j++) S[i][j] = 0.f;

#pragma unroll
        for (int ks = 0; ks < 4; ks++) {
            uint32_t Ah[4], Al[4];
            ldmx4(Ah, QHs + a_row + ks * 32);
            ldmx4(Al, QLs + a_row + ks * 32);
#pragma unroll
            for (int ntp = 0; ntp < 4; ntp++) {
                uint32_t Bh[4], Bl[4];
                uint32_t baddr = b_base + ntp * (16 * LDKB) + ks * 32;
                ldmx4(Bh, KHs + baddr);
                ldmx4(Bl, KLs + baddr);
                mma16816(S[2*ntp],   Ah, Bh[0], Bh[1]);
                mma16816(S[2*ntp],   Ah, Bl[0], Bl[1]);
                mma16816(S[2*ntp],   Al, Bh[0], Bh[1]);
                mma16816(S[2*ntp+1], Ah, Bh[2], Bh[3]);
                mma16816(S[2*ntp+1], Ah, Bl[2], Bl[3]);
                mma16816(S[2*ntp+1], Al, Bh[2], Bh[3]);
            }
        }

        // ---- exp2 softmax (no max shift) ----
#pragma unroll
        for (int nt = 0; nt < 8; nt++) {
            float p0 = ex2f(S[nt][0] * QKS);
            float p1 = ex2f(S[nt][1] * QKS);
            float p2 = ex2f(S[nt][2] * QKS);
            float p3 = ex2f(S[nt][3] * QKS);
            S[nt][0] = p0; S[nt][1] = p1; S[nt][2] = p2; S[nt][3] = p3;
            lsum0 += p0 + p1;
            lsum1 += p2 + p3;
        }

        // ---- O += P @ V (3-term split) ----
#pragma unroll
        for (int j = 0; j < 4; j++) {
            uint32_t Ph[4], Pl[4];
            split2(S[2*j][0],   S[2*j][1],   Ph[0], Pl[0]);
            split2(S[2*j][2],   S[2*j][3],   Ph[1], Pl[1]);
            split2(S[2*j+1][0], S[2*j+1][1], Ph[2], Pl[2]);
            split2(S[2*j+1][2], S[2*j+1][3], Ph[3], Pl[3]);
#pragma unroll
            for (int dtp = 0; dtp < 4; dtp++) {
                uint32_t Vh[4], Vl[4];
                uint32_t vaddr = b_base + dtp * (16 * LDKB) + j * 32;
                ldmx4(Vh, VHs + vaddr);
                ldmx4(Vl, VLs + vaddr);
                mma16816(O[2*dtp],   Ph, Vh[0], Vh[1]);
                mma16816(O[2*dtp],   Ph, Vl[0], Vl[1]);
                mma16816(O[2*dtp],   Pl, Vh[0], Vh[1]);
                mma16816(O[2*dtp+1], Ph, Vh[2], Vh[3]);
                mma16816(O[2*dtp+1], Ph, Vl[2], Vl[3]);
                mma16816(O[2*dtp+1], Pl, Vh[2], Vh[3]);
            }
        }
        __syncthreads();
    }

    // ---- Normalize + write ----
    lsum0 += __shfl_xor_sync(0xffffffffu, lsum0, 1);
    lsum0 += __shfl_xor_sync(0xffffffffu, lsum0, 2);
    lsum1 += __shfl_xor_sync(0xffffffffu, lsum1, 1);
    lsum1 += __shfl_xor_sync(0xffffffffu, lsum1, 2);
    float inv0 = 1.f / lsum0;
    float inv1 = 1.f / lsum1;

    int r0 = q0 + w * 16 + (lane >> 2);
    int r1 = r0 + 8;
#pragma unroll
    for (int dt = 0; dt < 8; dt++) {
        int c = dt * 8 + 2 * (lane & 3);
        float2 u0 = make_float2(O[dt][0] * inv0, O[dt][1] * inv0);
        float2 u1 = make_float2(O[dt][2] * inv1, O[dt][3] * inv1);
        *(float2*)&g_C[gbase + r0 * DMODEL + c] = u0;
        *(float2*)&g_C[gbase + r1 * DMODEL + c] = u1;
    }
}

// ---------------------------------------------------------------------------
extern "C" void kernel_launch(void* const* d_in, const int* in_sizes, int n_in,
                              void* d_out, int out_size)
{
    static bool inited = false;
    static float *dQ, *dK, *dV, *dC;
    if (!inited) {
        cudaGetSymbolAddress((void**)&dQ, g_Q);
        cudaGetSymbolAddress((void**)&dK, g_K);
        cudaGetSymbolAddress((void**)&dV, g_V);
        cudaGetSymbolAddress((void**)&dC, g_C);
        cudaFuncSetAttribute(attn_hmma,
                             cudaFuncAttributeMaxDynamicSharedMemorySize, SM_ATTN_BYTES);
        inited = true;
    }

    const float* x  = (const float*)d_in[0];
    const float* Wq = (const float*)d_in[1];
    const float* bq = (const float*)d_in[2];
    const float* Wk = (const float*)d_in[3];
    const float* bk = (const float*)d_in[4];
    const float* Wv = (const float*)d_in[5];
    const float* bv = (const float*)d_in[6];
    const float* Wo = (const float*)d_in[7];
    const float* bo = (const float*)d_in[8];
    float* out = (float*)d_out;

    dim3 gg(DMODEL / 128, MROWS / 128);   // (4, 64)
    gemm_hmma<<<gg, 256>>>(x,  Wq, bq, dQ);
    gemm_hmma<<<gg, 256>>>(x,  Wk, bk, dK);
    gemm_hmma<<<gg, 256>>>(x,  Wv, bv, dV);

    dim3 ga(SEQ / 128, BATCH * NHEADS);   // (32, 16)
    attn_hmma<<<ga, 256, SM_ATTN_BYTES>>>();

    gemm_hmma<<<gg, 256>>>(dC, Wo, bo, out);
}